// round 12
// baseline (speedup 1.0000x reference)
#include <cuda_runtime.h>

#define CIN  3
#define COUT 16
#define OD   62
#define OH   62
#define OW   62

typedef unsigned long long ull;

__device__ __forceinline__ void fma2(ull& acc, ull x, ull w) {
    asm("fma.rn.f32x2 %0, %1, %2, %0;" : "+l"(acc) : "l"(x), "l"(w));
}
__device__ __forceinline__ ull rep2(float a) {
    ull r;
    asm("mov.b64 %0, {%1, %1};" : "=l"(r) : "f"(a));
    return r;
}
__device__ __forceinline__ float2 unpk(ull v) {
    float2 r;
    asm("mov.b64 {%0, %1}, %2;" : "=f"(r.x), "=f"(r.y) : "l"(v));
    return r;
}

// Constant-memory weights: [pos(81)][pair(8)] = {w[2k], w[2k+1]} packed ull.
// Loaded via the constant-cache port -> zero LDS/L1tex traffic for weights.
__constant__ __align__(16) ull  cw[81 * 8];
__constant__ float cb[16];

// Staging buffers (device->constant copy done with cudaMemcpyToSymbolAsync).
__device__ __align__(16) ull  g_wp[81 * 8];
__device__ float g_bias[16];

__global__ void prep_weights(const float* __restrict__ wgt,
                             const float* __restrict__ bias)
{
    const int tid = threadIdx.x;
    for (int i = tid; i < 81 * 8; i += 128) {
        const int pos = i >> 3;
        const int k   = i & 7;
        const unsigned lo = __float_as_uint(wgt[(2 * k)     * 81 + pos]);
        const unsigned hi = __float_as_uint(wgt[(2 * k + 1) * 81 + pos]);
        g_wp[i] = ((ull)hi << 32) | (ull)lo;
    }
    if (tid < 16) g_bias[tid] = bias[tid];
}

// Fused Conv3d(3->16,k=3,valid) + bias + min over D + softmax over C.
// R10 body (one thread = (n,h',w',channel-group of 8), f32x2 over channel
// pairs, TD=4, kh unrolled) with weights moved from shared memory to
// __constant__ -> weight fetches leave the L1tex/LSU path entirely.
__global__ __launch_bounds__(128, 4)
void fused_conv_min_softmax(const float* __restrict__ x,
                            float* __restrict__ out)
{
    __shared__ float sred[2][64];

    const int tid = threadIdx.x;
    const int cg = tid >> 6;          // channel group 0/1 (channels cg*8..+7)
    const int wl = tid & 63;          // lane-w
    const bool active = (wl < OW);
    const int w = active ? wl : 0;    // clamp for safe addressing

    const int h = blockIdx.x;         // 0..61
    const int n = blockIdx.y;         // 0..15

    float mval[8];
#pragma unroll
    for (int c = 0; c < 8; c++) mval[c] = 3.402823466e38f;

    // x layout [ci][d][y][w]: strides 262144 / 4096 / 64
    const float* xbase = x + (size_t)n * (CIN * 262144) + h * 64 + w;
    const int cgo = cg * 4;           // pair offset within a tap

    // 16 depth tiles of 4: d0 = 0,4,...,56, then 58 (overlap; min idempotent)
#pragma unroll 1
    for (int t = 0; t < 16; t++) {
        const int d0 = (t < 15) ? (t << 2) : 58;

        ull acc[4][4];
#pragma unroll
        for (int d = 0; d < 4; d++)
#pragma unroll
            for (int pr = 0; pr < 4; pr++) acc[d][pr] = 0ull;

#pragma unroll 1
        for (int ci = 0; ci < CIN; ci++) {
            const float* cbp = xbase + ci * 262144 + d0 * 4096;

            // kh UNROLLED: 3 bodies with compile-time kh*64 offsets.
#pragma unroll
            for (int kh = 0; kh < 3; kh++) {
                const float* rp0 = cbp + kh * 64;

                // 6 input-depth rows cover kd(0..2) x depth-tile(0..3)
                ull xr[6][3];
#pragma unroll
                for (int r = 0; r < 6; r++) {
                    const float* rp = rp0 + r * 4096;
                    xr[r][0] = rep2(rp[0]);
                    xr[r][1] = rep2(rp[1]);
                    xr[r][2] = rep2(rp[2]);
                }

#pragma unroll
                for (int kd = 0; kd < 3; kd++) {
#pragma unroll
                    for (int kw = 0; kw < 3; kw++) {
                        const int pos = ci * 27 + kd * 9 + kh * 3 + kw;
                        // 2x LDC.128 from constant cache (separate port)
                        const ulonglong2* w2 =
                            (const ulonglong2*)&cw[pos * 8 + cgo];
                        const ulonglong2 wa = w2[0];
                        const ulonglong2 wb = w2[1];
#pragma unroll
                        for (int d = 0; d < 4; d++) {
                            const ull xv = xr[kd + d][kw];
                            fma2(acc[d][0], xv, wa.x);
                            fma2(acc[d][1], xv, wa.y);
                            fma2(acc[d][2], xv, wb.x);
                            fma2(acc[d][3], xv, wb.y);
                        }
                    }
                }
            }
        }

#pragma unroll
        for (int d = 0; d < 4; d++)
#pragma unroll
            for (int pr = 0; pr < 4; pr++) {
                const float2 v = unpk(acc[d][pr]);
                mval[2 * pr]     = fminf(mval[2 * pr],     v.x);
                mval[2 * pr + 1] = fminf(mval[2 * pr + 1], v.y);
            }
    }

    // bias + softmax over 16 channels, split across 2 threads (cg 0/1)
    float v[8];
    float mx = -3.402823466e38f;
#pragma unroll
    for (int c = 0; c < 8; c++) {
        v[c] = mval[c] + cb[cg * 8 + c];
        mx = fmaxf(mx, v[c]);
    }
    sred[cg][wl] = mx;
    __syncthreads();
    mx = fmaxf(sred[0][wl], sred[1][wl]);
    __syncthreads();

    float s = 0.f;
#pragma unroll
    for (int c = 0; c < 8; c++) {
        v[c] = __expf(v[c] - mx);
        s += v[c];
    }
    sred[cg][wl] = s;
    __syncthreads();
    const float inv = 1.0f / (sred[0][wl] + sred[1][wl]);

    if (active) {
        const int hw = h * OW + w;
#pragma unroll
        for (int c = 0; c < 8; c++) {
            out[(size_t)(n * COUT + cg * 8 + c) * (OH * OW) + hw] = v[c] * inv;
        }
    }
}

extern "C" void kernel_launch(void* const* d_in, const int* in_sizes, int n_in,
                              void* d_out, int out_size)
{
    const float* x    = (const float*)d_in[0];  // [16,3,64,64,64]
    const float* wgt  = (const float*)d_in[1];  // [16,3,3,3,3]
    const float* bias = (const float*)d_in[2];  // [16]
    float* out = (float*)d_out;                 // [16,16,62,62]

    // 1) transpose+pack weights into device staging
    prep_weights<<<1, 128>>>(wgt, bias);

    // 2) stage -> __constant__ (async D2D, graph-capturable)
    void* wp_addr = nullptr;
    void* b_addr  = nullptr;
    cudaGetSymbolAddress(&wp_addr, g_wp);
    cudaGetSymbolAddress(&b_addr,  g_bias);
    cudaMemcpyToSymbolAsync(cw, wp_addr, 81 * 8 * sizeof(ull), 0,
                            cudaMemcpyDeviceToDevice, 0);
    cudaMemcpyToSymbolAsync(cb, b_addr, 16 * sizeof(float), 0,
                            cudaMemcpyDeviceToDevice, 0);

    // 3) main fused kernel
    dim3 grid(OH, 16);   // (h', n)
    dim3 block(128);     // 64 w-lanes x 2 channel groups
    fused_conv_min_softmax<<<grid, block>>>(x, out);
}

// round 14
// speedup vs baseline: 1.8045x; 1.8045x over previous
#include <cuda_runtime.h>
#include <cstdint>

#define OH 62
#define OW 62

typedef uint32_t u32;

__device__ __forceinline__ u32 tf32r(float f) {   // fp32 -> tf32 round-to-nearest
    return (__float_as_uint(f) + 0x1000u) & 0xFFFFE000u;
}
__device__ __forceinline__ u32 smem_u32(const void* p) {
    u32 a;
    asm("{ .reg .u64 t; cvta.to.shared.u64 t, %1; cvt.u32.u64 %0, t; }"
        : "=r"(a) : "l"(p));
    return a;
}

// Fused Conv3d(3->16,k3,valid)+bias+minD+softmaxC via warp-level tf32 HMMA
// (mma.sync m16n8k8 — baseline PTX, compiles at compute_103).
// Block=(n,h), 128 thr = 4 warps; warp owns 16 w-pixels, loops all 62 depths.
// GEMM: M=w-pixels, N=16 couts, K=81 taps (pad 88 = 11 k-blocks of 8).
// A-frags read from a shifted-row smem slab (x rows, NOT im2col) via
// precomputed per-lane offsets; B-frags (weights) pre-arranged per-lane.
// k>=81 pad columns have ZERO weights, so A reads there are don't-care.
__global__ __launch_bounds__(128, 6)
void conv_hmma(const float* __restrict__ x,
               const float* __restrict__ wgt,
               const float* __restrict__ bias,
               float* __restrict__ out)
{
    // slab rows: [ci(3)][dslice(10)][kh(3)] x 68 floats (64 data + 4 zero pad)
    __shared__ float s_x[90 * 68];
    // B fragments: [kblk(11)][nb(2)][lane(32)][2]
    __shared__ float s_bf[11 * 2 * 32 * 2];
    __shared__ float s_min[64][16];

    const int tid  = threadIdx.x;
    const int warp = tid >> 5;
    const int lane = tid & 31;
    const int g    = lane >> 2;   // groupID
    const int t    = lane & 3;    // threadID_in_group
    const int w0   = warp << 4;   // warp's 16-pixel w tile
    const int h    = blockIdx.x;  // 0..61
    const int n    = blockIdx.y;  // 0..15

    // ---- stage B fragments (once): b0=(k=8j+t, n=8nb+g), b1=(k+4, n) ----
    for (int i = tid; i < 11 * 2 * 32; i += 128) {
        const int li  = i & 31;
        const int nbj = i >> 5;
        const int nb  = nbj & 1;
        const int j   = nbj >> 1;
        const int gi  = li >> 2, ti = li & 3;
        const int nn  = nb * 8 + gi;
        const int k0  = j * 8 + ti;
        const int k1  = k0 + 4;
        s_bf[i * 2]     = (k0 <= 80) ? __uint_as_float(tf32r(wgt[nn * 81 + k0])) : 0.f;
        s_bf[i * 2 + 1] = (k1 <= 80) ? __uint_as_float(tf32r(wgt[nn * 81 + k1])) : 0.f;
    }

    // ---- per-lane A-fragment offsets (bytes) for dloc=0 ----
    // A[p=w0+g][k] = slab[(ci*30 + (dloc+kd)*3 + kh)*68 + (w0+g+kw)]
    u32 off0[11], off2[11];
    {
        const u32 base = smem_u32(s_x);
#pragma unroll
        for (int j = 0; j < 11; j++) {
            int k = 8 * j + t;        if (k > 80) k = 80;   // pad k: weights=0
            int ci = k / 27, r = k % 27;
            int kd = r / 9, kh = (r % 9) / 3, kw = k % 3;
            off0[j] = base + (u32)(((ci * 30 + kd * 3 + kh) * 68 + w0 + g + kw) * 4);
            k = 8 * j + t + 4;        if (k > 80) k = 80;
            ci = k / 27; r = k % 27;
            kd = r / 9; kh = (r % 9) / 3; kw = k % 3;
            off2[j] = base + (u32)(((ci * 30 + kd * 3 + kh) * 68 + w0 + g + kw) * 4);
        }
    }
    const u32 bb = smem_u32(s_bf) + (u32)lane * 8u;

    float mn0[4], mn1[4];
#pragma unroll
    for (int i = 0; i < 4; i++) { mn0[i] = 3.402823466e38f; mn1[i] = 3.402823466e38f; }

    const float* xn = x + (size_t)n * 786432 + h * 64;

    // ---- 8 chunks of 8 depths: d0 = 0,8,...,48, then 54 (overlap; min idem) ----
#pragma unroll 1
    for (int ch = 0; ch < 8; ch++) {
        const int d0 = (ch < 7) ? (ch << 3) : 54;

        __syncthreads();   // protect previous chunk's slab reads
        // stage slab: 90 rows x 17 float4 (cols 64..67 zeroed)
        for (int i = tid; i < 90 * 17; i += 128) {
            const int r   = i / 17;
            const int pos = i - r * 17;
            const int ci = r / 30, rr = r % 30;
            const int dl = rr / 3, kh = rr % 3;
            float4 v = make_float4(0.f, 0.f, 0.f, 0.f);
            if (pos < 16) {
                v = *(const float4*)(xn + ci * 262144 + (d0 + dl) * 4096
                                        + kh * 64 + pos * 4);
                v.x = __uint_as_float(tf32r(v.x));
                v.y = __uint_as_float(tf32r(v.y));
                v.z = __uint_as_float(tf32r(v.z));
                v.w = __uint_as_float(tf32r(v.w));
            }
            *(float4*)&s_x[r * 68 + pos * 4] = v;
        }
        __syncthreads();

#pragma unroll 1
        for (int dl = 0; dl < 8; dl++) {
            float c0[4] = {0.f, 0.f, 0.f, 0.f};
            float c1[4] = {0.f, 0.f, 0.f, 0.f};
#pragma unroll
            for (int j = 0; j < 11; j++) {
                u32 a0, a1, a2, a3, b0, b1;
                asm volatile("ld.shared.b32 %0, [%1];"      : "=r"(a0) : "r"(off0[j]));
                asm volatile("ld.shared.b32 %0, [%1+32];"   : "=r"(a1) : "r"(off0[j]));
                asm volatile("ld.shared.b32 %0, [%1];"      : "=r"(a2) : "r"(off2[j]));
                asm volatile("ld.shared.b32 %0, [%1+32];"   : "=r"(a3) : "r"(off2[j]));
                asm volatile("ld.shared.v2.b32 {%0,%1}, [%2];"
                             : "=r"(b0), "=r"(b1) : "r"(bb + (u32)(j * 2) * 256u));
                asm volatile(
                    "mma.sync.aligned.m16n8k8.row.col.f32.tf32.tf32.f32 "
                    "{%0,%1,%2,%3}, {%4,%5,%6,%7}, {%8,%9}, {%0,%1,%2,%3};"
                    : "+f"(c0[0]), "+f"(c0[1]), "+f"(c0[2]), "+f"(c0[3])
                    : "r"(a0), "r"(a1), "r"(a2), "r"(a3), "r"(b0), "r"(b1));
                asm volatile("ld.shared.v2.b32 {%0,%1}, [%2];"
                             : "=r"(b0), "=r"(b1) : "r"(bb + (u32)(j * 2 + 1) * 256u));
                asm volatile(
                    "mma.sync.aligned.m16n8k8.row.col.f32.tf32.tf32.f32 "
                    "{%0,%1,%2,%3}, {%4,%5,%6,%7}, {%8,%9}, {%0,%1,%2,%3};"
                    : "+f"(c1[0]), "+f"(c1[1]), "+f"(c1[2]), "+f"(c1[3])
                    : "r"(a0), "r"(a1), "r"(a2), "r"(a3), "r"(b0), "r"(b1));
                off0[j] += 816u;   // next depth slice (3*68 floats)
                off2[j] += 816u;
            }
#pragma unroll
            for (int i = 0; i < 4; i++) {
                mn0[i] = fminf(mn0[i], c0[i]);
                mn1[i] = fminf(mn1[i], c1[i]);
            }
        }
        // rewind offsets to dloc=0 for next chunk's (restaged) slab
#pragma unroll
        for (int j = 0; j < 11; j++) { off0[j] -= 6528u; off2[j] -= 6528u; }
    }

    // ---- gather mins: thread (g,t) owns pixels w0+g, w0+g+8; couts {2t,2t+1}+8nb ----
    __syncthreads();
    s_min[w0 + g][2 * t]         = mn0[0];
    s_min[w0 + g][2 * t + 1]     = mn0[1];
    s_min[w0 + g + 8][2 * t]     = mn0[2];
    s_min[w0 + g + 8][2 * t + 1] = mn0[3];
    s_min[w0 + g][8 + 2 * t]         = mn1[0];
    s_min[w0 + g][8 + 2 * t + 1]     = mn1[1];
    s_min[w0 + g + 8][8 + 2 * t]     = mn1[2];
    s_min[w0 + g + 8][8 + 2 * t + 1] = mn1[3];
    __syncthreads();

    // ---- bias + softmax over 16 channels, one thread per valid pixel ----
    if (tid < OW) {
        float v[16];
        float mx = -3.402823466e38f;
#pragma unroll
        for (int c = 0; c < 16; c++) {
            v[c] = s_min[tid][c] + bias[c];
            mx = fmaxf(mx, v[c]);
        }
        float s = 0.f;
#pragma unroll
        for (int c = 0; c < 16; c++) {
            v[c] = __expf(v[c] - mx);
            s += v[c];
        }
        const float inv = 1.0f / s;
#pragma unroll
        for (int c = 0; c < 16; c++) {
            out[((size_t)(n * 16 + c) * OH + h) * OW + tid] = v[c] * inv;
        }
    }
}

extern "C" void kernel_launch(void* const* d_in, const int* in_sizes, int n_in,
                              void* d_out, int out_size)
{
    const float* x    = (const float*)d_in[0];  // [16,3,64,64,64]
    const float* wgt  = (const float*)d_in[1];  // [16,3,3,3,3]
    const float* bias = (const float*)d_in[2];  // [16]
    float* out = (float*)d_out;                 // [16,16,62,62]

    dim3 grid(OH, 16);   // (h, n)
    dim3 block(128);
    conv_hmma<<<grid, block>>>(x, wgt, bias, out);
}

// round 15
// speedup vs baseline: 2.2780x; 1.2624x over previous
#include <cuda_runtime.h>
#include <cstdint>

#define OH 62
#define OW 62
#define RS 72   // slab row stride in floats (72 mod 32 = 8 -> spread banks)

typedef uint32_t u32;

__device__ __forceinline__ u32 tf32r(float f) {   // fp32 -> tf32 round-to-nearest
    return (__float_as_uint(f) + 0x1000u) & 0xFFFFE000u;
}
__device__ __forceinline__ u32 smem_u32(const void* p) {
    u32 a;
    asm("{ .reg .u64 t; cvta.to.shared.u64 t, %1; cvt.u32.u64 %0, t; }"
        : "=r"(a) : "l"(p));
    return a;
}
__device__ __forceinline__ void hmma(float* c, const u32* a, u32 b0, u32 b1) {
    asm volatile(
        "mma.sync.aligned.m16n8k8.row.col.f32.tf32.tf32.f32 "
        "{%0,%1,%2,%3}, {%4,%5,%6,%7}, {%8,%9}, {%0,%1,%2,%3};"
        : "+f"(c[0]), "+f"(c[1]), "+f"(c[2]), "+f"(c[3])
        : "r"(a[0]), "r"(a[1]), "r"(a[2]), "r"(a[3]), "r"(b0), "r"(b1));
}

// Fused Conv3d(3->16,k3,valid)+bias+minD+softmaxC via warp tf32 HMMA.
// vs R14: operands SWAPPED — A = weights (M=16 couts) hoisted into 44
// registers (loop-invariant, zero LDS); B = pixels (N=8/MMA) from the
// shifted-row slab (2 LDS.32 per MMA). Slab row stride 72 floats spreads
// rows across banks {0,8,16,24}. 4 independent accumulation chains.
__global__ __launch_bounds__(128, 4)
void conv_hmma(const float* __restrict__ x,
               const float* __restrict__ wgt,
               const float* __restrict__ bias,
               float* __restrict__ out)
{
    // slab rows: [ci(3)][dslice(10)][kh(3)] x RS floats (64 data + 8 zero)
    __shared__ float s_x[90 * RS];
    __shared__ float s_min[64][16];

    const int tid  = threadIdx.x;
    const int warp = tid >> 5;
    const int lane = tid & 31;
    const int g    = lane >> 2;   // groupID
    const int t    = lane & 3;    // threadID_in_group
    const int w0   = warp << 4;   // warp's 16-pixel w tile
    const int h    = blockIdx.x;  // 0..61
    const int n    = blockIdx.y;  // 0..15

    // ---- A fragments (weights) -> registers, once ----
    // a0=W[g][k], a1=W[g+8][k], a2=W[g][k+4], a3=W[g+8][k+4], k=8j+t
    u32 wa[11][4];
#pragma unroll
    for (int j = 0; j < 11; j++) {
        const int k0 = 8 * j + t;
        const int k1 = k0 + 4;
        wa[j][0] = (k0 <= 80) ? tf32r(wgt[g * 81 + k0])       : 0u;
        wa[j][1] = (k0 <= 80) ? tf32r(wgt[(g + 8) * 81 + k0]) : 0u;
        wa[j][2] = (k1 <= 80) ? tf32r(wgt[g * 81 + k1])       : 0u;
        wa[j][3] = (k1 <= 80) ? tf32r(wgt[(g + 8) * 81 + k1]) : 0u;
    }

    // ---- per-lane B (pixel) offsets for dloc=0 ----
    // P[k][pix] = slab[(ci*30 + (dl+kd)*3 + kh)*RS + (pix + kw)], pix = w0+pg*8+g
    u32 offT[11], offT4[11];
    {
        const u32 base = smem_u32(s_x);
#pragma unroll
        for (int j = 0; j < 11; j++) {
            int k = 8 * j + t;        if (k > 80) k = 80;   // pad k: weights=0
            int ci = k / 27, r = k % 27;
            int kd = r / 9, kh = (r % 9) / 3, kw = k % 3;
            offT[j] = base + (u32)(((ci * 30 + kd * 3 + kh) * RS + w0 + g + kw) * 4);
            k = 8 * j + t + 4;        if (k > 80) k = 80;
            ci = k / 27; r = k % 27;
            kd = r / 9; kh = (r % 9) / 3; kw = k % 3;
            offT4[j] = base + (u32)(((ci * 30 + kd * 3 + kh) * RS + w0 + g + kw) * 4);
        }
    }

    // mins: mn[pg][i], D-fragment layout (m=cout, n=pixel)
    float mn0[4], mn1[4];
#pragma unroll
    for (int i = 0; i < 4; i++) { mn0[i] = 3.402823466e38f; mn1[i] = 3.402823466e38f; }

    const float* xn = x + (size_t)n * 786432 + h * 64;

    // ---- 8 chunks of 8 depths: d0 = 0,8,...,48, then 54 (overlap; min idem) ----
#pragma unroll 1
    for (int ch = 0; ch < 8; ch++) {
        const int d0 = (ch < 7) ? (ch << 3) : 54;

        __syncthreads();   // protect previous chunk's slab reads
        // stage slab: 90 rows x 18 float4 (cols 64..71 zeroed), tf32-rounded
        for (int i = tid; i < 90 * 18; i += 128) {
            const int r   = i / 18;
            const int pos = i - r * 18;
            const int ci = r / 30, rr = r % 30;
            const int dl = rr / 3, kh = rr % 3;
            float4 v = make_float4(0.f, 0.f, 0.f, 0.f);
            if (pos < 16) {
                v = *(const float4*)(xn + ci * 262144 + (d0 + dl) * 4096
                                        + kh * 64 + pos * 4);
                v.x = __uint_as_float(tf32r(v.x));
                v.y = __uint_as_float(tf32r(v.y));
                v.z = __uint_as_float(tf32r(v.z));
                v.w = __uint_as_float(tf32r(v.w));
            }
            *(float4*)&s_x[r * RS + pos * 4] = v;
        }
        __syncthreads();

#pragma unroll 1
        for (int dl = 0; dl < 8; dl++) {
            // 4 independent accumulation chains (pg x even/odd j)
            float cA0[4] = {0,0,0,0}, cB0[4] = {0,0,0,0};
            float cA1[4] = {0,0,0,0}, cB1[4] = {0,0,0,0};
#pragma unroll
            for (int j = 0; j < 11; j++) {
                u32 b00, b01, b10, b11;
                asm volatile("ld.shared.b32 %0, [%1];"    : "=r"(b00) : "r"(offT[j]));
                asm volatile("ld.shared.b32 %0, [%1];"    : "=r"(b01) : "r"(offT4[j]));
                asm volatile("ld.shared.b32 %0, [%1+32];" : "=r"(b10) : "r"(offT[j]));
                asm volatile("ld.shared.b32 %0, [%1+32];" : "=r"(b11) : "r"(offT4[j]));
                if ((j & 1) == 0) {
                    hmma(cA0, wa[j], b00, b01);
                    hmma(cA1, wa[j], b10, b11);
                } else {
                    hmma(cB0, wa[j], b00, b01);
                    hmma(cB1, wa[j], b10, b11);
                }
                offT[j]  += 3 * RS * 4;   // next depth slice
                offT4[j] += 3 * RS * 4;
            }
#pragma unroll
            for (int i = 0; i < 4; i++) {
                mn0[i] = fminf(mn0[i], cA0[i] + cB0[i]);
                mn1[i] = fminf(mn1[i], cA1[i] + cB1[i]);
            }
        }
        // rewind offsets for next chunk's restaged slab
#pragma unroll
        for (int j = 0; j < 11; j++) {
            offT[j]  -= 8 * 3 * RS * 4;
            offT4[j] -= 8 * 3 * RS * 4;
        }
    }

    // ---- scatter mins: thread (g,t) holds couts {g,g+8}, pixels {2t,2t+1}+pg*8 ----
    __syncthreads();
    s_min[w0 + 2 * t][g]          = mn0[0];
    s_min[w0 + 2 * t + 1][g]      = mn0[1];
    s_min[w0 + 2 * t][g + 8]      = mn0[2];
    s_min[w0 + 2 * t + 1][g + 8]  = mn0[3];
    s_min[w0 + 8 + 2 * t][g]         = mn1[0];
    s_min[w0 + 8 + 2 * t + 1][g]     = mn1[1];
    s_min[w0 + 8 + 2 * t][g + 8]     = mn1[2];
    s_min[w0 + 8 + 2 * t + 1][g + 8] = mn1[3];
    __syncthreads();

    // ---- bias + softmax over 16 channels, one thread per valid pixel ----
    if (tid < OW) {
        float v[16];
        float mx = -3.402823466e38f;
#pragma unroll
        for (int c = 0; c < 16; c++) {
            v[c] = s_min[tid][c] + bias[c];
            mx = fmaxf(mx, v[c]);
        }
        float s = 0.f;
#pragma unroll
        for (int c = 0; c < 16; c++) {
            v[c] = __expf(v[c] - mx);
            s += v[c];
        }
        const float inv = 1.0f / s;
#pragma unroll
        for (int c = 0; c < 16; c++) {
            out[((size_t)(n * 16 + c) * OH + h) * OW + tid] = v[c] * inv;
        }
    }
}

extern "C" void kernel_launch(void* const* d_in, const int* in_sizes, int n_in,
                              void* d_out, int out_size)
{
    const float* x    = (const float*)d_in[0];  // [16,3,64,64,64]
    const float* wgt  = (const float*)d_in[1];  // [16,3,3,3,3]
    const float* bias = (const float*)d_in[2];  // [16]
    float* out = (float*)d_out;                 // [16,16,62,62]

    dim3 grid(OH, 16);   // (h, n)
    dim3 block(128);
    conv_hmma<<<grid, block>>>(x, wgt, bias, out);
}

// round 16
// speedup vs baseline: 2.6641x; 1.1695x over previous
#include <cuda_runtime.h>
#include <cuda_fp16.h>
#include <cstdint>

#define OH 62
#define OW 62
#define RS 72   // slab row stride in half2 units (288 B = 8 banks mod 32)

typedef uint32_t u32;

__device__ __forceinline__ u32 smem_u32(const void* p) {
    u32 a;
    asm("{ .reg .u64 t; cvta.to.shared.u64 t, %1; cvt.u32.u64 %0, t; }"
        : "=r"(a) : "l"(p));
    return a;
}
__device__ __forceinline__ u32 h2pack(float a, float b) {
    const __half2 h = __floats2half2_rn(a, b);
    return *(const u32*)&h;
}
__device__ __forceinline__ void hmma16(float* c, const u32* a, u32 b0, u32 b1) {
    asm volatile(
        "mma.sync.aligned.m16n8k16.row.col.f32.f16.f16.f32 "
        "{%0,%1,%2,%3}, {%4,%5,%6,%7}, {%8,%9}, {%0,%1,%2,%3};"
        : "+f"(c[0]), "+f"(c[1]), "+f"(c[2]), "+f"(c[3])
        : "r"(a[0]), "r"(a[1]), "r"(a[2]), "r"(a[3]), "r"(b0), "r"(b1));
}

// Fused Conv3d(3->16,k3,valid)+bias+minD+softmaxC via fp16 HMMA m16n8k16
// (fp16 mantissa == tf32 mantissa -> same accuracy, half the instructions).
// A = weights (M=16 couts) in 28 registers; B = pixels from a half2-PAIR
// slab: slabP[row][w] = {x[w], x[w+1]} so adjacent-k B fragments are one
// aligned LDS.32. K = 112 = 27 taps x {kw0,kw1,kw2,pad(w=0 weights)}.
__global__ __launch_bounds__(128, 4)
void conv_hmma(const float* __restrict__ x,
               const float* __restrict__ wgt,
               const float* __restrict__ bias,
               float* __restrict__ out)
{
    // slab rows: [ci(3)][dslice(10)][kh(3)] x RS half2 entries
    __shared__ u32   s_x[90 * RS];
    __shared__ float s_min[64][16];

    const int tid  = threadIdx.x;
    const int warp = tid >> 5;
    const int lane = tid & 31;
    const int g    = lane >> 2;   // groupID
    const int t    = lane & 3;    // threadID_in_group
    const int w0   = warp << 4;   // warp's 16-pixel w tile
    const int h    = blockIdx.x;  // 0..61
    const int n    = blockIdx.y;  // 0..15

    // ---- A fragments (weights) -> registers, once ----
    // W(c, k): k = q*4+s, q=(ci,kd,kh) 0..26, s=kw (3 = zero pad)
    u32 wa[7][4];
#pragma unroll
    for (int j = 0; j < 7; j++) {
        const int k0 = 16 * j + 2 * t;
        float wv[2][4];   // [m-half][k offset 0,1,8,9]
#pragma unroll
        for (int u = 0; u < 4; u++) {
            const int k = k0 + ((u >> 1) << 3) + (u & 1);   // k0,k0+1,k0+8,k0+9
            const int q = k >> 2, s = k & 3;
            float f0 = 0.f, f1 = 0.f;
            if (s != 3 && q <= 26) {
                const int ci = q / 9, kd = (q % 9) / 3, kh = q % 3;
                f0 = wgt[g * 81 + ci * 27 + kd * 9 + kh * 3 + s];
                f1 = wgt[(g + 8) * 81 + ci * 27 + kd * 9 + kh * 3 + s];
            }
            wv[0][u] = f0; wv[1][u] = f1;
        }
        wa[j][0] = h2pack(wv[0][0], wv[0][1]);
        wa[j][1] = h2pack(wv[1][0], wv[1][1]);
        wa[j][2] = h2pack(wv[0][2], wv[0][3]);
        wa[j][3] = h2pack(wv[1][2], wv[1][3]);
    }

    // ---- per-lane B offsets (bytes) at dl=0 ----
    // b0: k=16j+2t -> q=4j+(t>>1), s=(t&1)*2 ; b1: q+2, same s
    u32 offb0[7], offb1[7];
    {
        const u32 base = smem_u32(s_x);
#pragma unroll
        for (int j = 0; j < 7; j++) {
            const int s0 = (t & 1) * 2;
            int q0 = 4 * j + (t >> 1); if (q0 > 26) q0 = 26;  // pad: weights=0
            int q1 = q0 + 2;           if (q1 > 26) q1 = 26;
            const int r0 = (q0 / 9) * 30 + ((q0 % 9) / 3) * 3 + (q0 % 3);
            const int r1 = (q1 / 9) * 30 + ((q1 % 9) / 3) * 3 + (q1 % 3);
            offb0[j] = base + (u32)((r0 * RS + w0 + g + s0) * 4);
            offb1[j] = base + (u32)((r1 * RS + w0 + g + s0) * 4);
        }
    }

    float mn0[4], mn1[4];
#pragma unroll
    for (int i = 0; i < 4; i++) { mn0[i] = 3.402823466e38f; mn1[i] = 3.402823466e38f; }

    const float* xn = x + (size_t)n * 786432 + h * 64;

    // ---- 8 chunks of 8 depths: d0 = 0,8,...,48, then 54 (overlap; min idem) ----
#pragma unroll 1
    for (int ch = 0; ch < 8; ch++) {
        const int d0 = (ch < 7) ? (ch << 3) : 54;

        __syncthreads();   // protect previous chunk's slab reads
        // stage slab: pairs {x[w], x[w+1]} as half2; cols 64..71 zeroed
        for (int i = tid; i < 90 * 18; i += 128) {
            const int r   = i / 18;
            const int pos = i - r * 18;
            const int ci = r / 30, rr = r % 30;
            const int dl = rr / 3, kh = rr % 3;
            uint4 o = make_uint4(0u, 0u, 0u, 0u);
            if (pos < 16) {
                const float* p = xn + ci * 262144 + (d0 + dl) * 4096
                                    + kh * 64 + pos * 4;
                const float4 v = *(const float4*)p;
                const float v4 = (pos < 15) ? p[4] : 0.f;
                o.x = h2pack(v.x, v.y);
                o.y = h2pack(v.y, v.z);
                o.z = h2pack(v.z, v.w);
                o.w = h2pack(v.w, v4);
            }
            *(uint4*)&s_x[r * RS + pos * 4] = o;
        }
        __syncthreads();

#pragma unroll 1
        for (int dl = 0; dl < 8; dl++) {
            // 4 independent chains: pixel-group x even/odd j
            float cE0[4] = {0,0,0,0}, cO0[4] = {0,0,0,0};
            float cE1[4] = {0,0,0,0}, cO1[4] = {0,0,0,0};
#pragma unroll
            for (int j = 0; j < 7; j++) {
                u32 b00, b01, b10, b11;
                asm volatile("ld.shared.b32 %0, [%1];"    : "=r"(b00) : "r"(offb0[j]));
                asm volatile("ld.shared.b32 %0, [%1];"    : "=r"(b01) : "r"(offb1[j]));
                asm volatile("ld.shared.b32 %0, [%1+32];" : "=r"(b10) : "r"(offb0[j]));
                asm volatile("ld.shared.b32 %0, [%1+32];" : "=r"(b11) : "r"(offb1[j]));
                if ((j & 1) == 0) {
                    hmma16(cE0, wa[j], b00, b01);
                    hmma16(cE1, wa[j], b10, b11);
                } else {
                    hmma16(cO0, wa[j], b00, b01);
                    hmma16(cO1, wa[j], b10, b11);
                }
                offb0[j] += 3 * RS * 4;   // next depth slice
                offb1[j] += 3 * RS * 4;
            }
#pragma unroll
            for (int i = 0; i < 4; i++) {
                mn0[i] = fminf(mn0[i], cE0[i] + cO0[i]);
                mn1[i] = fminf(mn1[i], cE1[i] + cO1[i]);
            }
        }
        // rewind for next chunk's restaged slab
#pragma unroll
        for (int j = 0; j < 7; j++) {
            offb0[j] -= 8 * 3 * RS * 4;
            offb1[j] -= 8 * 3 * RS * 4;
        }
    }

    // ---- scatter mins: lane(g,t): couts {g,g+8}, pixels {2t,2t+1} + pg*8 ----
    __syncthreads();
    s_min[w0 + 2 * t][g]         = mn0[0];
    s_min[w0 + 2 * t + 1][g]     = mn0[1];
    s_min[w0 + 2 * t][g + 8]     = mn0[2];
    s_min[w0 + 2 * t + 1][g + 8] = mn0[3];
    s_min[w0 + 8 + 2 * t][g]         = mn1[0];
    s_min[w0 + 8 + 2 * t + 1][g]     = mn1[1];
    s_min[w0 + 8 + 2 * t][g + 8]     = mn1[2];
    s_min[w0 + 8 + 2 * t + 1][g + 8] = mn1[3];
    __syncthreads();

    // ---- bias + softmax over 16 channels, one thread per valid pixel ----
    if (tid < OW) {
        float v[16];
        float mx = -3.402823466e38f;
#pragma unroll
        for (int c = 0; c < 16; c++) {
            v[c] = s_min[tid][c] + bias[c];
            mx = fmaxf(mx, v[c]);
        }
        float s = 0.f;
#pragma unroll
        for (int c = 0; c < 16; c++) {
            v[c] = __expf(v[c] - mx);
            s += v[c];
        }
        const float inv = 1.0f / s;
#pragma unroll
        for (int c = 0; c < 16; c++) {
            out[((size_t)(n * 16 + c) * OH + h) * OW + tid] = v[c] * inv;
        }
    }
}

extern "C" void kernel_launch(void* const* d_in, const int* in_sizes, int n_in,
                              void* d_out, int out_size)
{
    const float* x    = (const float*)d_in[0];  // [16,3,64,64,64]
    const float* wgt  = (const float*)d_in[1];  // [16,3,3,3,3]
    const float* bias = (const float*)d_in[2];  // [16]
    float* out = (float*)d_out;                 // [16,16,62,62]

    dim3 grid(OH, 16);   // (h, n)
    dim3 block(128);
    conv_hmma<<<grid, block>>>(x, wgt, bias, out);
}